// round 16
// baseline (speedup 1.0000x reference)
#include <cuda_runtime.h>
#include <cuda_fp16.h>
#include <cstdint>

// ---------------------------------------------------------------------------
// EncoderLayer R15: R14 + fp16-only out1 (no fp32 S2 round-trip) +
// O-proj split-K=4 (tail recovery). GEMM/attention cores unchanged.
// ---------------------------------------------------------------------------

#define M_TOK   8192
#define DMODEL  1024
#define DFF     4096
#define NHEAD   16
#define DHEAD   64
#define SEQ     2048
#define QKVS    3072
#define PSTRIDE ((long)M_TOK * DMODEL)

// fp32 scratch
__device__ float g_b3 [QKVS];
// fp16 split-K partials
__device__ __half g_Pf [4 * M_TOK * DMODEL];
// fp16 activations
__device__ __half g_Xf  [M_TOK * DMODEL];
__device__ __half g_QKVf[M_TOK * QKVS];
__device__ __half g_Cf  [M_TOK * DMODEL];
__device__ __half g_O1f [M_TOK * DMODEL];
__device__ __half g_H1f [M_TOK * DFF];
// fp16 transposed weights [N,K]
__device__ __half g_WQKV[QKVS * DMODEL];
__device__ __half g_WO  [DMODEL * DMODEL];
__device__ __half g_W1  [DFF * DMODEL];
__device__ __half g_W2  [DMODEL * DFF];

__device__ __forceinline__ uint32_t smem_u32(const void* p) {
    uint32_t a;
    asm("{ .reg .u64 t; cvta.to.shared.u64 t, %1; cvt.u32.u64 %0, t; }" : "=r"(a) : "l"(p));
    return a;
}
__device__ __forceinline__ void ldmat_x4(uint32_t* r, uint32_t addr) {
    asm volatile("ldmatrix.sync.aligned.m8n8.x4.shared.b16 {%0,%1,%2,%3}, [%4];"
                 : "=r"(r[0]), "=r"(r[1]), "=r"(r[2]), "=r"(r[3]) : "r"(addr));
}
__device__ __forceinline__ void ldmat_x4t(uint32_t* r, uint32_t addr) {
    asm volatile("ldmatrix.sync.aligned.m8n8.x4.trans.shared.b16 {%0,%1,%2,%3}, [%4];"
                 : "=r"(r[0]), "=r"(r[1]), "=r"(r[2]), "=r"(r[3]) : "r"(addr));
}
__device__ __forceinline__ void mma_f16(float* d, const uint32_t* a, const uint32_t* b) {
    asm volatile("mma.sync.aligned.m16n8k16.row.col.f32.f16.f16.f32 "
                 "{%0,%1,%2,%3}, {%4,%5,%6,%7}, {%8,%9}, {%0,%1,%2,%3};"
                 : "+f"(d[0]), "+f"(d[1]), "+f"(d[2]), "+f"(d[3])
                 : "r"(a[0]), "r"(a[1]), "r"(a[2]), "r"(a[3]), "r"(b[0]), "r"(b[1]));
}
__device__ __forceinline__ uint32_t pack_h2(float lo, float hi) {
    __half2 t = __floats2half2_rn(lo, hi);
    return *reinterpret_cast<uint32_t*>(&t);
}
__device__ __forceinline__ uint32_t exp2_h2(float a, float b) {
    __half2 t = __floats2half2_rn(a, b);
    uint32_t in = *reinterpret_cast<uint32_t*>(&t), out;
    asm volatile("ex2.approx.f16x2 %0, %1;" : "=r"(out) : "r"(in));
    return out;
}
#define CP16(dst, src) asm volatile("cp.async.cg.shared.global [%0], [%1], 16;" :: "r"(dst), "l"(src))
#define CP_COMMIT()    asm volatile("cp.async.commit_group;" ::: "memory")
#define CP_WAIT1()     asm volatile("cp.async.wait_group 1;" ::: "memory")
#define CP_WAIT0()     asm volatile("cp.async.wait_group 0;" ::: "memory")

#define SWZ128(row, bc) ((uint32_t)((row) * 128 + ((bc) ^ (((row) & 7) << 4))))

// softmax: p = 2^clamp(s*0.125*log2e - 2*log2e)
#define SM_C1 0.18033688011112043f
#define SM_C0 (-2.8853900817779268f)
#define SM_HI 11.541560327111707f
#define SM_LO (-17.312340490667562f)

// ---------------------------------------------------------------------------
// fp16 HMMA GEMM: BM=BN=128, BK=64, 256 thr, 64x32/warp, 3-stage.
// ---------------------------------------------------------------------------
#define GST 32768
#define OF_A 0
#define OF_B 16384
#define GEMM_SMEM (3 * GST)

__global__ void __launch_bounds__(256, 2) gemm_mma(
    const __half* __restrict__ A, const __half* __restrict__ B,
    const float* __restrict__ bias, float* __restrict__ C,
    __half* __restrict__ Cf, long zstride,
    int N, int K, int Ksl, int relu, int mode)
{
    extern __shared__ char smraw[];
    const uint32_t sb = smem_u32(smraw);

    const int tid = threadIdx.x;
    const int wid = tid >> 5, lid = tid & 31;
    const int m0 = blockIdx.y * 128, n0 = blockIdx.x * 128;
    const int z  = blockIdx.z;
    const long kzb = (long)z * Ksl;
    Cf += (long)z * zstride;
    const int wm = (wid >> 2) * 64;
    const int wn = (wid & 3) * 32;

    const int r  = tid >> 3;
    const int cb = (tid & 7) * 16;
    const int cg = (tid & 7) * 8;
    const uint32_t swz = SWZ128(r, cb);

    float acc[4][4][4];
#pragma unroll
    for (int mt = 0; mt < 4; mt++)
#pragma unroll
        for (int nt = 0; nt < 4; nt++)
#pragma unroll
            for (int f = 0; f < 4; f++) acc[mt][nt][f] = 0.f;

    const int lrow = lid & 15;
    const int lcb  = (lid >> 4) * 16;
    const int NC = Ksl >> 6;

    auto issue = [&](int i) {
        const uint32_t base = sb + (i % 3) * GST;
        const long k0 = kzb + (long)(i << 6);
        const long ra = (long)(m0 + r) * K + k0 + cg;
        const long rb = (long)(n0 + r) * K + k0 + cg;
#pragma unroll
        for (int rg = 0; rg < 4; rg++) {
            CP16(base + OF_A + swz + rg * 32 * 128, A + ra + (long)rg * 32 * K);
            CP16(base + OF_B + swz + rg * 32 * 128, B + rb + (long)rg * 32 * K);
        }
    };

    issue(0); CP_COMMIT();
    if (NC > 1) { issue(1); CP_COMMIT(); }

    for (int i = 0; i < NC; i++) {
        if (i + 1 < NC) CP_WAIT1(); else CP_WAIT0();
        __syncthreads();
        if (i + 2 < NC) { issue(i + 2); CP_COMMIT(); }

        const uint32_t base = sb + (i % 3) * GST;
        const uint32_t aB = base + OF_A, bB = base + OF_B;

#pragma unroll
        for (int k16 = 0; k16 < 4; k16++) {
            const int bc = k16 * 32 + lcb;
            uint32_t af[4][4];
#pragma unroll
            for (int mt = 0; mt < 4; mt++)
                ldmat_x4(af[mt], aB + SWZ128(wm + mt * 16 + lrow, bc));
            uint32_t bf[2][4];
#pragma unroll
            for (int np = 0; np < 2; np++)
                ldmat_x4(bf[np], bB + SWZ128(wn + np * 16 + lrow, bc));
#pragma unroll
            for (int mt = 0; mt < 4; mt++) {
#pragma unroll
                for (int nt = 0; nt < 4; nt++) {
                    uint32_t b2[2] = { bf[nt >> 1][nt & 1], bf[nt >> 1][(nt & 1) + 2] };
                    mma_f16(acc[mt][nt], af[mt], b2);
                }
            }
        }
    }

    const int g  = lid >> 2;
    const int tg = (lid & 3) * 2;
#pragma unroll
    for (int mt = 0; mt < 4; mt++) {
        const int row = m0 + wm + mt * 16 + g;
#pragma unroll
        for (int nt = 0; nt < 4; nt++) {
            const int col = n0 + wn + nt * 8 + tg;
            const float b0 = z ? 0.f : bias[col];
            const float b1 = z ? 0.f : bias[col + 1];
            float v0 = acc[mt][nt][0] + b0;
            float v1 = acc[mt][nt][1] + b1;
            float v2 = acc[mt][nt][2] + b0;
            float v3 = acc[mt][nt][3] + b1;
            if (relu) {
                v0 = fmaxf(v0, 0.f); v1 = fmaxf(v1, 0.f);
                v2 = fmaxf(v2, 0.f); v3 = fmaxf(v3, 0.f);
            }
            if (mode == 0) {
                C[(long)row * N + col]           = v0;
                C[(long)row * N + col + 1]       = v1;
                C[(long)(row + 8) * N + col]     = v2;
                C[(long)(row + 8) * N + col + 1] = v3;
            } else {
                *(uint32_t*)(Cf + (long)row * N + col)       = pack_h2(v0, v1);
                *(uint32_t*)(Cf + (long)(row + 8) * N + col) = pack_h2(v2, v3);
            }
        }
    }
}

// ---------------------------------------------------------------------------
// fp16 HMMA attention (R14): 128-key chunks, 2-stage pipeline,
// ex2.approx.f16x2 softmax, tensor-core row sums.
// ---------------------------------------------------------------------------
#define ATS 72
#define AQ    0
#define AKV0  18432
#define AKVST 36864
#define A_K   0
#define A_V   18432
#define ATTN_SMEM 92160

__global__ void __launch_bounds__(256, 2) attn_mma(
    const __half* __restrict__ QKVf, __half* __restrict__ Cf)
{
    extern __shared__ char smraw[];
    const uint32_t sb = smem_u32(smraw);

    const int tid = threadIdx.x;
    const int wid = tid >> 5, lid = tid & 31;
    const int bh = blockIdx.y;
    const int b = bh >> 4, h = bh & 15;
    const int q0 = blockIdx.x * 128;
    const long qbase = (long)(b * SEQ + q0) * QKVS + h * DHEAD;
    const long kbase = (long)(b * SEQ) * QKVS + DMODEL + h * DHEAD;
    const long vbase = kbase + DMODEL;

    for (int e = tid; e < 128 * 8; e += 256) {
        int row = e >> 3, cgp = (e & 7) * 8;
        const uint32_t so = (uint32_t)(row * 144 + cgp * 2);
        *(uint4*)(smraw + AQ + so) = *(const uint4*)(QKVf + qbase + (long)row * QKVS + cgp);
    }

    auto issueKV = [&](int c) {
        const uint32_t base = sb + AKV0 + (c & 1) * AKVST;
#pragma unroll
        for (int e0 = 0; e0 < 4; e0++) {
            const int e = tid + e0 * 256;
            const int row = e >> 3, cgp = (e & 7) * 8;
            const uint32_t so = (uint32_t)(row * 144 + cgp * 2);
            CP16(base + A_K + so, QKVf + kbase + (long)(c * 128 + row) * QKVS + cgp);
            CP16(base + A_V + so, QKVf + vbase + (long)(c * 128 + row) * QKVS + cgp);
        }
    };

    const int mrow = wid * 16;
    const int lrow = lid & 15;
    const int lcol = (lid >> 4) * 8;
    const uint32_t qB = sb + AQ;
    const uint32_t ones2 = 0x3C003C00u;
    const uint32_t onesf[2] = { ones2, ones2 };

    float acc[8][4];
#pragma unroll
    for (int nt = 0; nt < 8; nt++)
#pragma unroll
        for (int f = 0; f < 4; f++) acc[nt][f] = 0.f;
    float dden[4] = {0.f, 0.f, 0.f, 0.f};

    const int NKC = SEQ / 128;
    issueKV(0); CP_COMMIT();

    for (int c = 0; c < NKC; c++) {
        CP_WAIT0();
        __syncthreads();
        if (c + 1 < NKC) { issueKV(c + 1); CP_COMMIT(); }

        const uint32_t stg = sb + AKV0 + (c & 1) * AKVST;

#pragma unroll
        for (int half = 0; half < 2; half++) {
            const uint32_t kB = stg + A_K + half * 64 * 144;
            const uint32_t vB = stg + A_V + half * 64 * 144;

            float S[8][4];
#pragma unroll
            for (int nt = 0; nt < 8; nt++)
#pragma unroll
                for (int f = 0; f < 4; f++) S[nt][f] = 0.f;

#pragma unroll
            for (int k16 = 0; k16 < 4; k16++) {
                uint32_t aF[4];
                ldmat_x4(aF, qB + ((mrow + lrow) * ATS + k16 * 16 + lcol) * 2);
#pragma unroll
                for (int np = 0; np < 4; np++) {
                    uint32_t bF[4];
                    ldmat_x4(bF, kB + ((np * 16 + lrow) * ATS + k16 * 16 + lcol) * 2);
                    uint32_t f0[2] = { bF[0], bF[2] }, f1[2] = { bF[1], bF[3] };
                    mma_f16(S[2 * np],     aF, f0);
                    mma_f16(S[2 * np + 1], aF, f1);
                }
            }

            uint32_t P[4][4];
#pragma unroll
            for (int nt = 0; nt < 8; nt++) {
                float t0 = fminf(fmaxf(fmaf(S[nt][0], SM_C1, SM_C0), SM_LO), SM_HI);
                float t1 = fminf(fmaxf(fmaf(S[nt][1], SM_C1, SM_C0), SM_LO), SM_HI);
                float t2 = fminf(fmaxf(fmaf(S[nt][2], SM_C1, SM_C0), SM_LO), SM_HI);
                float t3 = fminf(fmaxf(fmaf(S[nt][3], SM_C1, SM_C0), SM_LO), SM_HI);
                uint32_t w0 = exp2_h2(t0, t1);
                uint32_t w1 = exp2_h2(t2, t3);
                const int j = nt >> 1;
                if ((nt & 1) == 0) { P[j][0] = w0; P[j][1] = w1; }
                else               { P[j][2] = w0; P[j][3] = w1; }
            }

#pragma unroll
            for (int j = 0; j < 4; j++) {
                mma_f16(dden, P[j], onesf);
#pragma unroll
                for (int np = 0; np < 4; np++) {
                    uint32_t vF[4];
                    ldmat_x4t(vF, vB + ((j * 16 + lrow) * ATS + np * 16 + lcol) * 2);
                    uint32_t f0[2] = { vF[0], vF[1] }, f1[2] = { vF[2], vF[3] };
                    mma_f16(acc[2 * np],     P[j], f0);
                    mma_f16(acc[2 * np + 1], P[j], f1);
                }
            }
        }
    }

    const float i0 = 1.f / dden[0];
    const float i1 = 1.f / dden[2];

    const int g  = lid >> 2;
    const int tg = (lid & 3) * 2;
    const long row0 = (long)(b * SEQ + q0 + mrow + g) * DMODEL + h * DHEAD;
    const long row1 = row0 + 8 * DMODEL;
#pragma unroll
    for (int nt = 0; nt < 8; nt++) {
        const int col = nt * 8 + tg;
        *(uint32_t*)(Cf + row0 + col) = pack_h2(acc[nt][0] * i0, acc[nt][1] * i0);
        *(uint32_t*)(Cf + row1 + col) = pack_h2(acc[nt][2] * i1, acc[nt][3] * i1);
    }
}

// ---------------------------------------------------------------------------
// Fused prep (R14)
// ---------------------------------------------------------------------------
__global__ void __launch_bounds__(256) prep_all(
    const float* __restrict__ x,
    const float* __restrict__ wq, const float* __restrict__ wk,
    const float* __restrict__ wv, const float* __restrict__ wo,
    const float* __restrict__ w1, const float* __restrict__ w2,
    const float* __restrict__ bq, const float* __restrict__ bk,
    const float* __restrict__ bv,
    __half* __restrict__ xf,
    __half* __restrict__ qkvt, __half* __restrict__ wot,
    __half* __restrict__ w1t,  __half* __restrict__ w2t,
    float* __restrict__ b3)
{
    const int bid = blockIdx.x;
    const int tidx = threadIdx.x;

    if (bid >= 12800) {
        int i = (bid - 12800) * 256 + tidx;
        if (i < DMODEL)           b3[i] = bq[i];
        else if (i < 2 * DMODEL)  b3[i] = bk[i - DMODEL];
        else if (i < 3 * DMODEL)  b3[i] = bv[i - 2 * DMODEL];
        return;
    }
    if (bid >= 12288) {
        const long n4 = (long)M_TOK * DMODEL / 4;
        long i = (long)(bid - 12288) * 256 + tidx;
        const long stride = 512L * 256;
        for (; i < n4; i += stride) {
            float4 v = ((const float4*)x)[i];
            uint2 p = { pack_h2(v.x, v.y), pack_h2(v.z, v.w) };
            ((uint2*)xf)[i] = p;
        }
        return;
    }

    const float* W;
    __half* dst;
    int K, N, bn, bk2;
    if (bid < 3072) {
        const int seg = bid >> 10, t = bid & 1023;
        W = seg == 0 ? wq : (seg == 1 ? wk : wv);
        dst = qkvt + (long)seg * DMODEL * DMODEL;
        K = DMODEL; N = DMODEL; bn = (t & 31) * 32; bk2 = (t >> 5) * 32;
    } else if (bid < 4096) {
        const int t = bid - 3072;
        W = wo; dst = wot;
        K = DMODEL; N = DMODEL; bn = (t & 31) * 32; bk2 = (t >> 5) * 32;
    } else if (bid < 8192) {
        const int t = bid - 4096;
        W = w1; dst = w1t;
        K = DMODEL; N = DFF; bn = (t & 127) * 32; bk2 = (t >> 7) * 32;
    } else {
        const int t = bid - 8192;
        W = w2; dst = w2t;
        K = DFF; N = DMODEL; bn = (t & 31) * 32; bk2 = (t >> 5) * 32;
    }

    __shared__ float tbuf[32][33];
    const int xx = tidx & 31, yy = tidx >> 5;
#pragma unroll
    for (int r = 0; r < 32; r += 8)
        tbuf[yy + r][xx] = W[(long)(bk2 + yy + r) * N + bn + xx];
    __syncthreads();
#pragma unroll
    for (int r = 0; r < 32; r += 8)
        dst[(long)(bn + yy + r) * K + bk2 + xx] = __float2half_rn(tbuf[xx][yy + r]);
}

// ---------------------------------------------------------------------------
// out = LayerNorm(base + sum of nparts fp16 partials) * gamma + beta
// base: fp32 A (if non-null) else fp16 Ah. Outputs optional fp32 / fp16.
// ---------------------------------------------------------------------------
__global__ __launch_bounds__(256) void add_ln_kernel(
    const float* __restrict__ A, const __half* __restrict__ Ah,
    const __half* __restrict__ P, int nparts,
    const float* __restrict__ gamma, const float* __restrict__ beta,
    float* __restrict__ out, __half* __restrict__ ohf)
{
    __shared__ float red[2];
    const int row = blockIdx.x;
    const int tid = threadIdx.x;

    float4 v;
    if (A) {
        v = ((const float4*)(A + (long)row * DMODEL))[tid];
    } else {
        uint2 hv = ((const uint2*)(Ah + (long)row * DMODEL))[tid];
        float2 f0 = __half22float2(*reinterpret_cast<__half2*>(&hv.x));
        float2 f1 = __half22float2(*reinterpret_cast<__half2*>(&hv.y));
        v = make_float4(f0.x, f0.y, f1.x, f1.y);
    }
    for (int p = 0; p < nparts; p++) {
        uint2 hv = ((const uint2*)(P + p * PSTRIDE + (long)row * DMODEL))[tid];
        float2 f0 = __half22float2(*reinterpret_cast<__half2*>(&hv.x));
        float2 f1 = __half22float2(*reinterpret_cast<__half2*>(&hv.y));
        v.x += f0.x; v.y += f0.y; v.z += f1.x; v.w += f1.y;
    }

    float s  = v.x + v.y + v.z + v.w;
    float sq = v.x * v.x + v.y * v.y + v.z * v.z + v.w * v.w;
#pragma unroll
    for (int o = 16; o; o >>= 1) {
        s  += __shfl_xor_sync(~0u, s,  o);
        sq += __shfl_xor_sync(~0u, sq, o);
    }
    const int w = tid >> 5, l = tid & 31;
    __shared__ float ws[8], wq2[8];
    if (l == 0) { ws[w] = s; wq2[w] = sq; }
    __syncthreads();
    if (tid < 32) {
        float s2 = (tid < 8) ? ws[tid] : 0.f;
        float q2 = (tid < 8) ? wq2[tid] : 0.f;
#pragma unroll
        for (int o = 4; o; o >>= 1) {
            s2 += __shfl_xor_sync(~0u, s2, o);
            q2 += __shfl_xor_sync(~0u, q2, o);
        }
        if (tid == 0) { red[0] = s2; red[1] = q2; }
    }
    __syncthreads();
    float mean = red[0] * (1.f / DMODEL);
    float var  = red[1] * (1.f / DMODEL) - mean * mean;
    float rs   = rsqrtf(var + 1e-8f);

    float4 g  = ((const float4*)gamma)[tid];
    float4 be = ((const float4*)beta)[tid];
    float4 o4;
    o4.x = (v.x - mean) * rs * g.x + be.x;
    o4.y = (v.y - mean) * rs * g.y + be.y;
    o4.z = (v.z - mean) * rs * g.z + be.z;
    o4.w = (v.w - mean) * rs * g.w + be.w;
    if (out)
        ((float4*)(out + (long)row * DMODEL))[tid] = o4;
    if (ohf) {
        uint2 hv = { pack_h2(o4.x, o4.y), pack_h2(o4.z, o4.w) };
        ((uint2*)(ohf + (long)row * DMODEL))[tid] = hv;
    }
}

// ---------------------------------------------------------------------------
extern "C" void kernel_launch(void* const* d_in, const int* in_sizes, int n_in,
                              void* d_out, int out_size)
{
    const float* x  = (const float*)d_in[0];
    const float* wq = (const float*)d_in[1];
    const float* bq = (const float*)d_in[2];
    const float* wk = (const float*)d_in[3];
    const float* bk = (const float*)d_in[4];
    const float* wv = (const float*)d_in[5];
    const float* bv = (const float*)d_in[6];
    const float* wo = (const float*)d_in[7];
    const float* bo = (const float*)d_in[8];
    const float* w1 = (const float*)d_in[9];
    const float* b1 = (const float*)d_in[10];
    const float* w2 = (const float*)d_in[11];
    const float* b2 = (const float*)d_in[12];
    const float* ga = (const float*)d_in[13];
    const float* be = (const float*)d_in[14];
    float* out = (float*)d_out;

    float *b3;
    __half *Pf, *Xf, *QKVf, *Cf, *O1f, *H1f, *WQKV, *WO, *W1, *W2;
    cudaGetSymbolAddress((void**)&b3,   g_b3);
    cudaGetSymbolAddress((void**)&Pf,   g_Pf);
    cudaGetSymbolAddress((void**)&Xf,   g_Xf);
    cudaGetSymbolAddress((void**)&QKVf, g_QKVf);
    cudaGetSymbolAddress((void**)&Cf,   g_Cf);
    cudaGetSymbolAddress((void**)&O1f,  g_O1f);
    cudaGetSymbolAddress((void**)&H1f,  g_H1f);
    cudaGetSymbolAddress((void**)&WQKV, g_WQKV);
    cudaGetSymbolAddress((void**)&WO,   g_WO);
    cudaGetSymbolAddress((void**)&W1,   g_W1);
    cudaGetSymbolAddress((void**)&W2,   g_W2);

    cudaFuncSetAttribute(gemm_mma, cudaFuncAttributeMaxDynamicSharedMemorySize, GEMM_SMEM);
    cudaFuncSetAttribute(attn_mma, cudaFuncAttributeMaxDynamicSharedMemorySize, ATTN_SMEM);

    dim3 blk(256);
    dim3 gQKV(QKVS / 128, M_TOK / 128, 1);
    dim3 gProjZ4(DMODEL / 128, M_TOK / 128, 4);
    dim3 gF1(DFF / 128, M_TOK / 128, 1);

    // fused prep
    prep_all<<<12812, blk>>>(x, wq, wk, wv, wo, w1, w2, bq, bk, bv,
                             Xf, WQKV, WO, W1, W2, b3);

    // fused QKV projection -> fp16
    gemm_mma<<<gQKV, blk, GEMM_SMEM>>>(Xf, WQKV, b3, nullptr,
                                       QKVf, 0, QKVS, DMODEL, DMODEL, 0, 1);

    // attention -> fp16 ctx
    dim3 gAttn(SEQ / 128, 4 * NHEAD);
    attn_mma<<<gAttn, blk, ATTN_SMEM>>>(QKVf, Cf);

    // O projection, split-K=4 -> fp16 partials
    gemm_mma<<<gProjZ4, blk, GEMM_SMEM>>>(Cf, WO, bo, nullptr,
                                          Pf, PSTRIDE, DMODEL, DMODEL, DMODEL / 4, 0, 1);

    // out1 = LN(x + p0..p3) -> fp16 only
    add_ln_kernel<<<M_TOK, blk>>>(x, nullptr, Pf, 4, ga, be, nullptr, O1f);

    // FFN1 -> relu -> fp16
    gemm_mma<<<gF1, blk, GEMM_SMEM>>>(O1f, W1, b1, nullptr,
                                      H1f, 0, DFF, DMODEL, DMODEL, 1, 1);

    // FFN2, split-K=4 -> fp16 partials
    gemm_mma<<<gProjZ4, blk, GEMM_SMEM>>>(H1f, W2, b2, nullptr,
                                          Pf, PSTRIDE, DMODEL, DFF, DFF / 4, 0, 1);

    // out = LN(out1_fp16 + p0..p3) -> fp32
    add_ln_kernel<<<M_TOK, blk>>>(nullptr, O1f, Pf, 4, ga, be, out, nullptr);
}

// round 17
// speedup vs baseline: 1.0120x; 1.0120x over previous
#include <cuda_runtime.h>
#include <cuda_fp16.h>
#include <cstdint>

// ---------------------------------------------------------------------------
// EncoderLayer R16: R15 with O-proj reverted to split-K=2 (NC=8 pipeline;
// split-K=4 at NC=4 measurably regressed). FFN2 stays split-K=4.
// fp16-only out1, fused prep, R14 attention.
// ---------------------------------------------------------------------------

#define M_TOK   8192
#define DMODEL  1024
#define DFF     4096
#define NHEAD   16
#define DHEAD   64
#define SEQ     2048
#define QKVS    3072
#define PSTRIDE ((long)M_TOK * DMODEL)

// fp32 scratch
__device__ float g_b3 [QKVS];
// fp16 split-K partials
__device__ __half g_Pf [4 * M_TOK * DMODEL];
// fp16 activations
__device__ __half g_Xf  [M_TOK * DMODEL];
__device__ __half g_QKVf[M_TOK * QKVS];
__device__ __half g_Cf  [M_TOK * DMODEL];
__device__ __half g_O1f [M_TOK * DMODEL];
__device__ __half g_H1f [M_TOK * DFF];
// fp16 transposed weights [N,K]
__device__ __half g_WQKV[QKVS * DMODEL];
__device__ __half g_WO  [DMODEL * DMODEL];
__device__ __half g_W1  [DFF * DMODEL];
__device__ __half g_W2  [DMODEL * DFF];

__device__ __forceinline__ uint32_t smem_u32(const void* p) {
    uint32_t a;
    asm("{ .reg .u64 t; cvta.to.shared.u64 t, %1; cvt.u32.u64 %0, t; }" : "=r"(a) : "l"(p));
    return a;
}
__device__ __forceinline__ void ldmat_x4(uint32_t* r, uint32_t addr) {
    asm volatile("ldmatrix.sync.aligned.m8n8.x4.shared.b16 {%0,%1,%2,%3}, [%4];"
                 : "=r"(r[0]), "=r"(r[1]), "=r"(r[2]), "=r"(r[3]) : "r"(addr));
}
__device__ __forceinline__ void ldmat_x4t(uint32_t* r, uint32_t addr) {
    asm volatile("ldmatrix.sync.aligned.m8n8.x4.trans.shared.b16 {%0,%1,%2,%3}, [%4];"
                 : "=r"(r[0]), "=r"(r[1]), "=r"(r[2]), "=r"(r[3]) : "r"(addr));
}
__device__ __forceinline__ void mma_f16(float* d, const uint32_t* a, const uint32_t* b) {
    asm volatile("mma.sync.aligned.m16n8k16.row.col.f32.f16.f16.f32 "
                 "{%0,%1,%2,%3}, {%4,%5,%6,%7}, {%8,%9}, {%0,%1,%2,%3};"
                 : "+f"(d[0]), "+f"(d[1]), "+f"(d[2]), "+f"(d[3])
                 : "r"(a[0]), "r"(a[1]), "r"(a[2]), "r"(a[3]), "r"(b[0]), "r"(b[1]));
}
__device__ __forceinline__ uint32_t pack_h2(float lo, float hi) {
    __half2 t = __floats2half2_rn(lo, hi);
    return *reinterpret_cast<uint32_t*>(&t);
}
__device__ __forceinline__ uint32_t exp2_h2(float a, float b) {
    __half2 t = __floats2half2_rn(a, b);
    uint32_t in = *reinterpret_cast<uint32_t*>(&t), out;
    asm volatile("ex2.approx.f16x2 %0, %1;" : "=r"(out) : "r"(in));
    return out;
}
#define CP16(dst, src) asm volatile("cp.async.cg.shared.global [%0], [%1], 16;" :: "r"(dst), "l"(src))
#define CP_COMMIT()    asm volatile("cp.async.commit_group;" ::: "memory")
#define CP_WAIT1()     asm volatile("cp.async.wait_group 1;" ::: "memory")
#define CP_WAIT0()     asm volatile("cp.async.wait_group 0;" ::: "memory")

#define SWZ128(row, bc) ((uint32_t)((row) * 128 + ((bc) ^ (((row) & 7) << 4))))

// softmax: p = 2^clamp(s*0.125*log2e - 2*log2e)
#define SM_C1 0.18033688011112043f
#define SM_C0 (-2.8853900817779268f)
#define SM_HI 11.541560327111707f
#define SM_LO (-17.312340490667562f)

// ---------------------------------------------------------------------------
// fp16 HMMA GEMM: BM=BN=128, BK=64, 256 thr, 64x32/warp, 3-stage.
// ---------------------------------------------------------------------------
#define GST 32768
#define OF_A 0
#define OF_B 16384
#define GEMM_SMEM (3 * GST)

__global__ void __launch_bounds__(256, 2) gemm_mma(
    const __half* __restrict__ A, const __half* __restrict__ B,
    const float* __restrict__ bias, float* __restrict__ C,
    __half* __restrict__ Cf, long zstride,
    int N, int K, int Ksl, int relu, int mode)
{
    extern __shared__ char smraw[];
    const uint32_t sb = smem_u32(smraw);

    const int tid = threadIdx.x;
    const int wid = tid >> 5, lid = tid & 31;
    const int m0 = blockIdx.y * 128, n0 = blockIdx.x * 128;
    const int z  = blockIdx.z;
    const long kzb = (long)z * Ksl;
    Cf += (long)z * zstride;
    const int wm = (wid >> 2) * 64;
    const int wn = (wid & 3) * 32;

    const int r  = tid >> 3;
    const int cb = (tid & 7) * 16;
    const int cg = (tid & 7) * 8;
    const uint32_t swz = SWZ128(r, cb);

    float acc[4][4][4];
#pragma unroll
    for (int mt = 0; mt < 4; mt++)
#pragma unroll
        for (int nt = 0; nt < 4; nt++)
#pragma unroll
            for (int f = 0; f < 4; f++) acc[mt][nt][f] = 0.f;

    const int lrow = lid & 15;
    const int lcb  = (lid >> 4) * 16;
    const int NC = Ksl >> 6;

    auto issue = [&](int i) {
        const uint32_t base = sb + (i % 3) * GST;
        const long k0 = kzb + (long)(i << 6);
        const long ra = (long)(m0 + r) * K + k0 + cg;
        const long rb = (long)(n0 + r) * K + k0 + cg;
#pragma unroll
        for (int rg = 0; rg < 4; rg++) {
            CP16(base + OF_A + swz + rg * 32 * 128, A + ra + (long)rg * 32 * K);
            CP16(base + OF_B + swz + rg * 32 * 128, B + rb + (long)rg * 32 * K);
        }
    };

    issue(0); CP_COMMIT();
    if (NC > 1) { issue(1); CP_COMMIT(); }

    for (int i = 0; i < NC; i++) {
        if (i + 1 < NC) CP_WAIT1(); else CP_WAIT0();
        __syncthreads();
        if (i + 2 < NC) { issue(i + 2); CP_COMMIT(); }

        const uint32_t base = sb + (i % 3) * GST;
        const uint32_t aB = base + OF_A, bB = base + OF_B;

#pragma unroll
        for (int k16 = 0; k16 < 4; k16++) {
            const int bc = k16 * 32 + lcb;
            uint32_t af[4][4];
#pragma unroll
            for (int mt = 0; mt < 4; mt++)
                ldmat_x4(af[mt], aB + SWZ128(wm + mt * 16 + lrow, bc));
            uint32_t bf[2][4];
#pragma unroll
            for (int np = 0; np < 2; np++)
                ldmat_x4(bf[np], bB + SWZ128(wn + np * 16 + lrow, bc));
#pragma unroll
            for (int mt = 0; mt < 4; mt++) {
#pragma unroll
                for (int nt = 0; nt < 4; nt++) {
                    uint32_t b2[2] = { bf[nt >> 1][nt & 1], bf[nt >> 1][(nt & 1) + 2] };
                    mma_f16(acc[mt][nt], af[mt], b2);
                }
            }
        }
    }

    const int g  = lid >> 2;
    const int tg = (lid & 3) * 2;
#pragma unroll
    for (int mt = 0; mt < 4; mt++) {
        const int row = m0 + wm + mt * 16 + g;
#pragma unroll
        for (int nt = 0; nt < 4; nt++) {
            const int col = n0 + wn + nt * 8 + tg;
            const float b0 = z ? 0.f : bias[col];
            const float b1 = z ? 0.f : bias[col + 1];
            float v0 = acc[mt][nt][0] + b0;
            float v1 = acc[mt][nt][1] + b1;
            float v2 = acc[mt][nt][2] + b0;
            float v3 = acc[mt][nt][3] + b1;
            if (relu) {
                v0 = fmaxf(v0, 0.f); v1 = fmaxf(v1, 0.f);
                v2 = fmaxf(v2, 0.f); v3 = fmaxf(v3, 0.f);
            }
            if (mode == 0) {
                C[(long)row * N + col]           = v0;
                C[(long)row * N + col + 1]       = v1;
                C[(long)(row + 8) * N + col]     = v2;
                C[(long)(row + 8) * N + col + 1] = v3;
            } else {
                *(uint32_t*)(Cf + (long)row * N + col)       = pack_h2(v0, v1);
                *(uint32_t*)(Cf + (long)(row + 8) * N + col) = pack_h2(v2, v3);
            }
        }
    }
}

// ---------------------------------------------------------------------------
// fp16 HMMA attention (R14): 128-key chunks, 2-stage pipeline,
// ex2.approx.f16x2 softmax, tensor-core row sums.
// ---------------------------------------------------------------------------
#define ATS 72
#define AQ    0
#define AKV0  18432
#define AKVST 36864
#define A_K   0
#define A_V   18432
#define ATTN_SMEM 92160

__global__ void __launch_bounds__(256, 2) attn_mma(
    const __half* __restrict__ QKVf, __half* __restrict__ Cf)
{
    extern __shared__ char smraw[];
    const uint32_t sb = smem_u32(smraw);

    const int tid = threadIdx.x;
    const int wid = tid >> 5, lid = tid & 31;
    const int bh = blockIdx.y;
    const int b = bh >> 4, h = bh & 15;
    const int q0 = blockIdx.x * 128;
    const long qbase = (long)(b * SEQ + q0) * QKVS + h * DHEAD;
    const long kbase = (long)(b * SEQ) * QKVS + DMODEL + h * DHEAD;
    const long vbase = kbase + DMODEL;

    for (int e = tid; e < 128 * 8; e += 256) {
        int row = e >> 3, cgp = (e & 7) * 8;
        const uint32_t so = (uint32_t)(row * 144 + cgp * 2);
        *(uint4*)(smraw + AQ + so) = *(const uint4*)(QKVf + qbase + (long)row * QKVS + cgp);
    }

    auto issueKV = [&](int c) {
        const uint32_t base = sb + AKV0 + (c & 1) * AKVST;
#pragma unroll
        for (int e0 = 0; e0 < 4; e0++) {
            const int e = tid + e0 * 256;
            const int row = e >> 3, cgp = (e & 7) * 8;
            const uint32_t so = (uint32_t)(row * 144 + cgp * 2);
            CP16(base + A_K + so, QKVf + kbase + (long)(c * 128 + row) * QKVS + cgp);
            CP16(base + A_V + so, QKVf + vbase + (long)(c * 128 + row) * QKVS + cgp);
        }
    };

    const int mrow = wid * 16;
    const int lrow = lid & 15;
    const int lcol = (lid >> 4) * 8;
    const uint32_t qB = sb + AQ;
    const uint32_t ones2 = 0x3C003C00u;
    const uint32_t onesf[2] = { ones2, ones2 };

    float acc[8][4];
#pragma unroll
    for (int nt = 0; nt < 8; nt++)
#pragma unroll
        for (int f = 0; f < 4; f++) acc[nt][f] = 0.f;
    float dden[4] = {0.f, 0.f, 0.f, 0.f};

    const int NKC = SEQ / 128;
    issueKV(0); CP_COMMIT();

    for (int c = 0; c < NKC; c++) {
        CP_WAIT0();
        __syncthreads();
        if (c + 1 < NKC) { issueKV(c + 1); CP_COMMIT(); }

        const uint32_t stg = sb + AKV0 + (c & 1) * AKVST;

#pragma unroll
        for (int half = 0; half < 2; half++) {
            const uint32_t kB = stg + A_K + half * 64 * 144;
            const uint32_t vB = stg + A_V + half * 64 * 144;

            float S[8][4];
#pragma unroll
            for (int nt = 0; nt < 8; nt++)
#pragma unroll
                for (int f = 0; f < 4; f++) S[nt][f] = 0.f;

#pragma unroll
            for (int k16 = 0; k16 < 4; k16++) {
                uint32_t aF[4];
                ldmat_x4(aF, qB + ((mrow + lrow) * ATS + k16 * 16 + lcol) * 2);
#pragma unroll
                for (int np = 0; np < 4; np++) {
                    uint32_t bF[4];
                    ldmat_x4(bF, kB + ((np * 16 + lrow) * ATS + k16 * 16 + lcol) * 2);
                    uint32_t f0[2] = { bF[0], bF[2] }, f1[2] = { bF[1], bF[3] };
                    mma_f16(S[2 * np],     aF, f0);
                    mma_f16(S[2 * np + 1], aF, f1);
                }
            }

            uint32_t P[4][4];
#pragma unroll
            for (int nt = 0; nt < 8; nt++) {
                float t0 = fminf(fmaxf(fmaf(S[nt][0], SM_C1, SM_C0), SM_LO), SM_HI);
                float t1 = fminf(fmaxf(fmaf(S[nt][1], SM_C1, SM_C0), SM_LO), SM_HI);
                float t2 = fminf(fmaxf(fmaf(S[nt][2], SM_C1, SM_C0), SM_LO), SM_HI);
                float t3 = fminf(fmaxf(fmaf(S[nt][3], SM_C1, SM_C0), SM_LO), SM_HI);
                uint32_t w0 = exp2_h2(t0, t1);
                uint32_t w1 = exp2_h2(t2, t3);
                const int j = nt >> 1;
                if ((nt & 1) == 0) { P[j][0] = w0; P[j][1] = w1; }
                else               { P[j][2] = w0; P[j][3] = w1; }
            }

#pragma unroll
            for (int j = 0; j < 4; j++) {
                mma_f16(dden, P[j], onesf);
#pragma unroll
                for (int np = 0; np < 4; np++) {
                    uint32_t vF[4];
                    ldmat_x4t(vF, vB + ((j * 16 + lrow) * ATS + np * 16 + lcol) * 2);
                    uint32_t f0[2] = { vF[0], vF[1] }, f1[2] = { vF[2], vF[3] };
                    mma_f16(acc[2 * np],     P[j], f0);
                    mma_f16(acc[2 * np + 1], P[j], f1);
                }
            }
        }
    }

    const float i0 = 1.f / dden[0];
    const float i1 = 1.f / dden[2];

    const int g  = lid >> 2;
    const int tg = (lid & 3) * 2;
    const long row0 = (long)(b * SEQ + q0 + mrow + g) * DMODEL + h * DHEAD;
    const long row1 = row0 + 8 * DMODEL;
#pragma unroll
    for (int nt = 0; nt < 8; nt++) {
        const int col = nt * 8 + tg;
        *(uint32_t*)(Cf + row0 + col) = pack_h2(acc[nt][0] * i0, acc[nt][1] * i0);
        *(uint32_t*)(Cf + row1 + col) = pack_h2(acc[nt][2] * i1, acc[nt][3] * i1);
    }
}

// ---------------------------------------------------------------------------
// Fused prep
// ---------------------------------------------------------------------------
__global__ void __launch_bounds__(256) prep_all(
    const float* __restrict__ x,
    const float* __restrict__ wq, const float* __restrict__ wk,
    const float* __restrict__ wv, const float* __restrict__ wo,
    const float* __restrict__ w1, const float* __restrict__ w2,
    const float* __restrict__ bq, const float* __restrict__ bk,
    const float* __restrict__ bv,
    __half* __restrict__ xf,
    __half* __restrict__ qkvt, __half* __restrict__ wot,
    __half* __restrict__ w1t,  __half* __restrict__ w2t,
    float* __restrict__ b3)
{
    const int bid = blockIdx.x;
    const int tidx = threadIdx.x;

    if (bid >= 12800) {
        int i = (bid - 12800) * 256 + tidx;
        if (i < DMODEL)           b3[i] = bq[i];
        else if (i < 2 * DMODEL)  b3[i] = bk[i - DMODEL];
        else if (i < 3 * DMODEL)  b3[i] = bv[i - 2 * DMODEL];
        return;
    }
    if (bid >= 12288) {
        const long n4 = (long)M_TOK * DMODEL / 4;
        long i = (long)(bid - 12288) * 256 + tidx;
        const long stride = 512L * 256;
        for (; i < n4; i += stride) {
            float4 v = ((const float4*)x)[i];
            uint2 p = { pack_h2(v.x, v.y), pack_h2(v.z, v.w) };
            ((uint2*)xf)[i] = p;
        }
        return;
    }

    const float* W;
    __half* dst;
    int K, N, bn, bk2;
    if (bid < 3072) {
        const int seg = bid >> 10, t = bid & 1023;
        W = seg == 0 ? wq : (seg == 1 ? wk : wv);
        dst = qkvt + (long)seg * DMODEL * DMODEL;
        K = DMODEL; N = DMODEL; bn = (t & 31) * 32; bk2 = (t >> 5) * 32;
    } else if (bid < 4096) {
        const int t = bid - 3072;
        W = wo; dst = wot;
        K = DMODEL; N = DMODEL; bn = (t & 31) * 32; bk2 = (t >> 5) * 32;
    } else if (bid < 8192) {
        const int t = bid - 4096;
        W = w1; dst = w1t;
        K = DMODEL; N = DFF; bn = (t & 127) * 32; bk2 = (t >> 7) * 32;
    } else {
        const int t = bid - 8192;
        W = w2; dst = w2t;
        K = DFF; N = DMODEL; bn = (t & 31) * 32; bk2 = (t >> 5) * 32;
    }

    __shared__ float tbuf[32][33];
    const int xx = tidx & 31, yy = tidx >> 5;
#pragma unroll
    for (int r = 0; r < 32; r += 8)
        tbuf[yy + r][xx] = W[(long)(bk2 + yy + r) * N + bn + xx];
    __syncthreads();
#pragma unroll
    for (int r = 0; r < 32; r += 8)
        dst[(long)(bn + yy + r) * K + bk2 + xx] = __float2half_rn(tbuf[xx][yy + r]);
}

// ---------------------------------------------------------------------------
// out = LayerNorm(base + sum of nparts fp16 partials) * gamma + beta
// ---------------------------------------------------------------------------
__global__ __launch_bounds__(256) void add_ln_kernel(
    const float* __restrict__ A, const __half* __restrict__ Ah,
    const __half* __restrict__ P, int nparts,
    const float* __restrict__ gamma, const float* __restrict__ beta,
    float* __restrict__ out, __half* __restrict__ ohf)
{
    __shared__ float red[2];
    const int row = blockIdx.x;
    const int tid = threadIdx.x;

    float4 v;
    if (A) {
        v = ((const float4*)(A + (long)row * DMODEL))[tid];
    } else {
        uint2 hv = ((const uint2*)(Ah + (long)row * DMODEL))[tid];
        float2 f0 = __half22float2(*reinterpret_cast<__half2*>(&hv.x));
        float2 f1 = __half22float2(*reinterpret_cast<__half2*>(&hv.y));
        v = make_float4(f0.x, f0.y, f1.x, f1.y);
    }
    for (int p = 0; p < nparts; p++) {
        uint2 hv = ((const uint2*)(P + p * PSTRIDE + (long)row * DMODEL))[tid];
        float2 f0 = __half22float2(*reinterpret_cast<__half2*>(&hv.x));
        float2 f1 = __half22float2(*reinterpret_cast<__half2*>(&hv.y));
        v.x += f0.x; v.y += f0.y; v.z += f1.x; v.w += f1.y;
    }

    float s  = v.x + v.y + v.z + v.w;
    float sq = v.x * v.x + v.y * v.y + v.z * v.z + v.w * v.w;
#pragma unroll
    for (int o = 16; o; o >>= 1) {
        s  += __shfl_xor_sync(~0u, s,  o);
        sq += __shfl_xor_sync(~0u, sq, o);
    }
    const int w = tid >> 5, l = tid & 31;
    __shared__ float ws[8], wq2[8];
    if (l == 0) { ws[w] = s; wq2[w] = sq; }
    __syncthreads();
    if (tid < 32) {
        float s2 = (tid < 8) ? ws[tid] : 0.f;
        float q2 = (tid < 8) ? wq2[tid] : 0.f;
#pragma unroll
        for (int o = 4; o; o >>= 1) {
            s2 += __shfl_xor_sync(~0u, s2, o);
            q2 += __shfl_xor_sync(~0u, q2, o);
        }
        if (tid == 0) { red[0] = s2; red[1] = q2; }
    }
    __syncthreads();
    float mean = red[0] * (1.f / DMODEL);
    float var  = red[1] * (1.f / DMODEL) - mean * mean;
    float rs   = rsqrtf(var + 1e-8f);

    float4 g  = ((const float4*)gamma)[tid];
    float4 be = ((const float4*)beta)[tid];
    float4 o4;
    o4.x = (v.x - mean) * rs * g.x + be.x;
    o4.y = (v.y - mean) * rs * g.y + be.y;
    o4.z = (v.z - mean) * rs * g.z + be.z;
    o4.w = (v.w - mean) * rs * g.w + be.w;
    if (out)
        ((float4*)(out + (long)row * DMODEL))[tid] = o4;
    if (ohf) {
        uint2 hv = { pack_h2(o4.x, o4.y), pack_h2(o4.z, o4.w) };
        ((uint2*)(ohf + (long)row * DMODEL))[tid] = hv;
    }
}

// ---------------------------------------------------------------------------
extern "C" void kernel_launch(void* const* d_in, const int* in_sizes, int n_in,
                              void* d_out, int out_size)
{
    const float* x  = (const float*)d_in[0];
    const float* wq = (const float*)d_in[1];
    const float* bq = (const float*)d_in[2];
    const float* wk = (const float*)d_in[3];
    const float* bk = (const float*)d_in[4];
    const float* wv = (const float*)d_in[5];
    const float* bv = (const float*)d_in[6];
    const float* wo = (const float*)d_in[7];
    const float* bo = (const float*)d_in[8];
    const float* w1 = (const float*)d_in[9];
    const float* b1 = (const float*)d_in[10];
    const float* w2 = (const float*)d_in[11];
    const float* b2 = (const float*)d_in[12];
    const float* ga = (const float*)d_in[13];
    const float* be = (const float*)d_in[14];
    float* out = (float*)d_out;

    float *b3;
    __half *Pf, *Xf, *QKVf, *Cf, *O1f, *H1f, *WQKV, *WO, *W1, *W2;
    cudaGetSymbolAddress((void**)&b3,   g_b3);
    cudaGetSymbolAddress((void**)&Pf,   g_Pf);
    cudaGetSymbolAddress((void**)&Xf,   g_Xf);
    cudaGetSymbolAddress((void**)&QKVf, g_QKVf);
    cudaGetSymbolAddress((void**)&Cf,   g_Cf);
    cudaGetSymbolAddress((void**)&O1f,  g_O1f);
    cudaGetSymbolAddress((void**)&H1f,  g_H1f);
    cudaGetSymbolAddress((void**)&WQKV, g_WQKV);
    cudaGetSymbolAddress((void**)&WO,   g_WO);
    cudaGetSymbolAddress((void**)&W1,   g_W1);
    cudaGetSymbolAddress((void**)&W2,   g_W2);

    cudaFuncSetAttribute(gemm_mma, cudaFuncAttributeMaxDynamicSharedMemorySize, GEMM_SMEM);
    cudaFuncSetAttribute(attn_mma, cudaFuncAttributeMaxDynamicSharedMemorySize, ATTN_SMEM);

    dim3 blk(256);
    dim3 gQKV(QKVS / 128, M_TOK / 128, 1);
    dim3 gProjZ2(DMODEL / 128, M_TOK / 128, 2);
    dim3 gProjZ4(DMODEL / 128, M_TOK / 128, 4);
    dim3 gF1(DFF / 128, M_TOK / 128, 1);

    // fused prep
    prep_all<<<12812, blk>>>(x, wq, wk, wv, wo, w1, w2, bq, bk, bv,
                             Xf, WQKV, WO, W1, W2, b3);

    // fused QKV projection -> fp16
    gemm_mma<<<gQKV, blk, GEMM_SMEM>>>(Xf, WQKV, b3, nullptr,
                                       QKVf, 0, QKVS, DMODEL, DMODEL, 0, 1);

    // attention -> fp16 ctx
    dim3 gAttn(SEQ / 128, 4 * NHEAD);
    attn_mma<<<gAttn, blk, ATTN_SMEM>>>(QKVf, Cf);

    // O projection, split-K=2 (NC=8) -> fp16 partials
    gemm_mma<<<gProjZ2, blk, GEMM_SMEM>>>(Cf, WO, bo, nullptr,
                                          Pf, PSTRIDE, DMODEL, DMODEL, DMODEL / 2, 0, 1);

    // out1 = LN(x + p0 + p1) -> fp16 only
    add_ln_kernel<<<M_TOK, blk>>>(x, nullptr, Pf, 2, ga, be, nullptr, O1f);

    // FFN1 -> relu -> fp16
    gemm_mma<<<gF1, blk, GEMM_SMEM>>>(O1f, W1, b1, nullptr,
                                      H1f, 0, DFF, DMODEL, DMODEL, 1, 1);

    // FFN2, split-K=4 (NC=16) -> fp16 partials
    gemm_mma<<<gProjZ4, blk, GEMM_SMEM>>>(H1f, W2, b2, nullptr,
                                          Pf, PSTRIDE, DMODEL, DFF, DFF / 4, 0, 1);

    // out = LN(out1_fp16 + p0..p3) -> fp32
    add_ln_kernel<<<M_TOK, blk>>>(nullptr, O1f, Pf, 4, ga, be, out, nullptr);
}